// round 2
// baseline (speedup 1.0000x reference)
#include <cuda_runtime.h>
#include <math.h>

#define BATCH 4
#define CK    512
#define AREA  4096
#define GROUPS 32
#define CPG   (CK / GROUPS)      // 16 channels per group

// ---------------- scratch (device globals; no allocation) ----------------
__device__ float g_xn[BATCH * CK * AREA];                 // 32 MB  normalized input
__device__ float g_q [BATCH * CK * AREA];                 // 32 MB
__device__ float g_k [BATCH * CK * AREA];                 // 32 MB
__device__ float g_v [BATCH * CK * AREA];                 // 32 MB
__device__ float g_o [BATCH * CK * AREA];                 // 32 MB  attn output (pre-proj)
__device__ float g_s [(size_t)BATCH * AREA * AREA];       // 256 MB attn logits / probs

// ---------------- GroupNorm ----------------
// One block per (b, g). Group data is a contiguous 16*4096 = 65536-float chunk.
__global__ void groupnorm_kernel(const float* __restrict__ net,
                                 const float* __restrict__ scale,
                                 const float* __restrict__ bias,
                                 float* __restrict__ out) {
    const int grp = blockIdx.x;                 // b*GROUPS + g
    const int nelem = CPG * AREA;               // 65536
    const float* src = net + (size_t)grp * nelem;
    float* dst = out + (size_t)grp * nelem;

    float s = 0.f, ss = 0.f;
    for (int i = threadIdx.x; i < nelem; i += blockDim.x) {
        float x = src[i];
        s += x; ss += x * x;
    }
    __shared__ float red[64];
    #pragma unroll
    for (int o = 16; o; o >>= 1) {
        s  += __shfl_xor_sync(0xffffffffu, s,  o);
        ss += __shfl_xor_sync(0xffffffffu, ss, o);
    }
    int wid = threadIdx.x >> 5, lid = threadIdx.x & 31;
    if (lid == 0) { red[wid] = s; red[wid + 32] = ss; }
    __syncthreads();
    if (wid == 0) {
        int nw = blockDim.x >> 5;
        s  = (lid < nw) ? red[lid] : 0.f;
        ss = (lid < nw) ? red[lid + 32] : 0.f;
        #pragma unroll
        for (int o = 16; o; o >>= 1) {
            s  += __shfl_xor_sync(0xffffffffu, s,  o);
            ss += __shfl_xor_sync(0xffffffffu, ss, o);
        }
        if (lid == 0) { red[0] = s; red[1] = ss; }
    }
    __syncthreads();
    const float inv_n = 1.f / (float)nelem;
    float mean = red[0] * inv_n;
    float var  = red[1] * inv_n - mean * mean;
    float rs   = rsqrtf(var + 1e-6f);
    int g = grp & (GROUPS - 1);

    for (int i = threadIdx.x; i < nelem; i += blockDim.x) {
        int cl = i >> 12;                       // i / AREA
        int c  = g * CPG + cl;
        dst[i] = (src[i] - mean) * rs * scale[c] + bias[c];
    }
}

// ---------------- Row softmax over 4096 (in place) ----------------
__global__ void softmax_kernel(float* __restrict__ p) {
    float* r = p + (size_t)blockIdx.x * AREA;
    const int t = threadIdx.x;                  // 256 threads, 16 elems each
    float v[16];
    float mx = -1e30f;
    #pragma unroll
    for (int j = 0; j < 16; j++) { v[j] = r[t + j * 256]; mx = fmaxf(mx, v[j]); }

    __shared__ float red[8];
    #pragma unroll
    for (int o = 16; o; o >>= 1) mx = fmaxf(mx, __shfl_xor_sync(0xffffffffu, mx, o));
    int wid = t >> 5, lid = t & 31;
    if (lid == 0) red[wid] = mx;
    __syncthreads();
    mx = red[lid & 7];
    #pragma unroll
    for (int o = 4; o; o >>= 1) mx = fmaxf(mx, __shfl_xor_sync(0xffffffffu, mx, o));

    float sum = 0.f;
    #pragma unroll
    for (int j = 0; j < 16; j++) { v[j] = __expf(v[j] - mx); sum += v[j]; }
    #pragma unroll
    for (int o = 16; o; o >>= 1) sum += __shfl_xor_sync(0xffffffffu, sum, o);
    if (lid == 0) red[wid] = sum;
    __syncthreads();
    sum = red[lid & 7];
    #pragma unroll
    for (int o = 4; o; o >>= 1) sum += __shfl_xor_sync(0xffffffffu, sum, o);

    float inv = 1.f / sum;
    #pragma unroll
    for (int j = 0; j < 16; j++) r[t + j * 256] = v[j] * inv;
}

// ---------------- Generic batched GEMM ----------------
// C[b](M x N, row-major, ldc) = alpha * op(A[b]) * op(B[b]) [+ bias[m]] [+ res[b](m,n)]
// TA: A stored [K, M] (element (m,k) at A[k*lda+m]); else [M, K] at A[m*lda+k]
// TB: B stored [N, K] (element (k,n) at B[n*ldb+k]); else [K, N] at B[k*ldb+n]
// Tiles: 128x128x8, 256 threads, 8x8 per thread (split 64+64 fragments).
// All problem dims here are multiples of the tile sizes, so no bounds checks.
#define BM 128
#define BN 128
#define BKK 8

template<bool TA, bool TB, bool HAS_BIAS, bool HAS_RES>
__global__ void __launch_bounds__(256, 2)
gemm_kernel(const float* __restrict__ A, size_t sA,
            const float* __restrict__ B, size_t sB,
            float* __restrict__ C, size_t sC,
            int K, int lda, int ldb, int ldc, float alpha,
            const float* __restrict__ bias,
            const float* __restrict__ res, size_t sR)
{
    const int bz = blockIdx.z;
    A += sA * bz; B += sB * bz; C += sC * bz;
    if (HAS_RES) res += sR * bz;
    const int m0 = blockIdx.y * BM;
    const int n0 = blockIdx.x * BN;

    __shared__ float As[BKK][BM];
    __shared__ float Bs[BKK][BN];

    const int tid = threadIdx.x;
    const int tx = tid & 15, ty = tid >> 4;

    float acc[8][8];
    #pragma unroll
    for (int i = 0; i < 8; i++)
        #pragma unroll
        for (int j = 0; j < 8; j++) acc[i][j] = 0.f;

    for (int k0 = 0; k0 < K; k0 += BKK) {
        if (TA) {   // contiguous in m: coalesced float4
            int kk = tid >> 5;
            int mm = (tid & 31) << 2;
            *(float4*)&As[kk][mm] =
                *(const float4*)(A + (size_t)(k0 + kk) * lda + m0 + mm);
        } else {    // contiguous in k: float4 along k, transpose into smem
            int mm = tid >> 1;
            int kk = (tid & 1) << 2;
            float4 va = *(const float4*)(A + (size_t)(m0 + mm) * lda + k0 + kk);
            As[kk + 0][mm] = va.x; As[kk + 1][mm] = va.y;
            As[kk + 2][mm] = va.z; As[kk + 3][mm] = va.w;
        }
        if (TB) {
            int nn = tid >> 1;
            int kk = (tid & 1) << 2;
            float4 vb = *(const float4*)(B + (size_t)(n0 + nn) * ldb + k0 + kk);
            Bs[kk + 0][nn] = vb.x; Bs[kk + 1][nn] = vb.y;
            Bs[kk + 2][nn] = vb.z; Bs[kk + 3][nn] = vb.w;
        } else {
            int kk = tid >> 5;
            int nn = (tid & 31) << 2;
            *(float4*)&Bs[kk][nn] =
                *(const float4*)(B + (size_t)(k0 + kk) * ldb + n0 + nn);
        }
        __syncthreads();

        #pragma unroll
        for (int kk = 0; kk < BKK; kk++) {
            float ra[8], rb[8];
            *(float4*)&ra[0] = *(const float4*)&As[kk][ty * 4];
            *(float4*)&ra[4] = *(const float4*)&As[kk][64 + ty * 4];
            *(float4*)&rb[0] = *(const float4*)&Bs[kk][tx * 4];
            *(float4*)&rb[4] = *(const float4*)&Bs[kk][64 + tx * 4];
            #pragma unroll
            for (int i = 0; i < 8; i++)
                #pragma unroll
                for (int j = 0; j < 8; j++)
                    acc[i][j] = fmaf(ra[i], rb[j], acc[i][j]);
        }
        __syncthreads();
    }

    #pragma unroll
    for (int i = 0; i < 8; i++) {
        int m = m0 + ((i & 4) ? 64 : 0) + ty * 4 + (i & 3);
        float bm = HAS_BIAS ? bias[m] : 0.f;
        #pragma unroll
        for (int j = 0; j < 8; j++) {
            int n = n0 + ((j & 4) ? 64 : 0) + tx * 4 + (j & 3);
            float val = acc[i][j] * alpha + bm;
            if (HAS_RES) val += res[(size_t)m * ldc + n];
            C[(size_t)m * ldc + n] = val;
        }
    }
}

// ---------------- launch ----------------
extern "C" void kernel_launch(void* const* d_in, const int* in_sizes, int n_in,
                              void* d_out, int out_size) {
    const float* net = (const float*)d_in[0];
    const float* gsc = (const float*)d_in[1];
    const float* gbi = (const float*)d_in[2];
    const float* wq  = (const float*)d_in[3];
    const float* bq  = (const float*)d_in[4];
    const float* wk  = (const float*)d_in[5];
    const float* bk  = (const float*)d_in[6];
    const float* wv  = (const float*)d_in[7];
    const float* bv  = (const float*)d_in[8];
    const float* wo  = (const float*)d_in[9];
    const float* bo  = (const float*)d_in[10];
    float* out = (float*)d_out;

    float *xn, *q, *k, *v, *o, *s;
    cudaGetSymbolAddress((void**)&xn, g_xn);
    cudaGetSymbolAddress((void**)&q,  g_q);
    cudaGetSymbolAddress((void**)&k,  g_k);
    cudaGetSymbolAddress((void**)&v,  g_v);
    cudaGetSymbolAddress((void**)&o,  g_o);
    cudaGetSymbolAddress((void**)&s,  g_s);

    const size_t sBC = (size_t)CK * AREA;        // per-batch feature stride
    const size_t sS  = (size_t)AREA * AREA;      // per-batch attn stride
    const float attn_scale = 0.04419417382415922f;   // 512^-0.5

    groupnorm_kernel<<<BATCH * GROUPS, 512>>>(net, gsc, gbi, xn);

    dim3 blk(256);
    dim3 grdW(AREA / BN, CK / BM, BATCH);        // (32, 4, 4)
    dim3 grdS(AREA / BN, AREA / BM, BATCH);      // (32, 32, 4)

    // q/k/v = W @ xn + b   (A=[M,K] row-major, B=[K,N] row-major)
    gemm_kernel<false, false, true, false><<<grdW, blk>>>(
        wq, 0, xn, sBC, q, sBC, CK, CK, AREA, AREA, 1.f, bq, nullptr, 0);
    gemm_kernel<false, false, true, false><<<grdW, blk>>>(
        wk, 0, xn, sBC, k, sBC, CK, CK, AREA, AREA, 1.f, bk, nullptr, 0);
    gemm_kernel<false, false, true, false><<<grdW, blk>>>(
        wv, 0, xn, sBC, v, sBC, CK, CK, AREA, AREA, 1.f, bv, nullptr, 0);

    // S = (q^T k) * scale   (A stored [K=C, M=area], B stored [K=C, N=area])
    gemm_kernel<true, false, false, false><<<grdS, blk>>>(
        q, sBC, k, sBC, s, sS, CK, AREA, AREA, AREA, attn_scale, nullptr, nullptr, 0);

    softmax_kernel<<<BATCH * AREA, 256>>>(s);

    // O = v @ p^T   (A=v [M=C, K=area] row-major, B=p stored [N=area, K=area])
    gemm_kernel<false, true, false, false><<<grdW, blk>>>(
        v, sBC, s, sS, o, sBC, AREA, AREA, AREA, AREA, 1.f, nullptr, nullptr, 0);

    // out = wo @ O + bo + net
    gemm_kernel<false, false, true, true><<<grdW, blk>>>(
        wo, 0, o, sBC, out, sBC, CK, CK, AREA, AREA, 1.f, bo, net, sBC);
}

// round 3
// speedup vs baseline: 4.6308x; 4.6308x over previous
#include <cuda_runtime.h>
#include <cuda_bf16.h>
#include <math.h>
#include <stdint.h>

#define BATCH 4
#define CK    512
#define AREA  4096
#define GROUPS 32
#define CPG   16

typedef __nv_bfloat16 bf16;

// ---------------- scratch (device globals; no allocation) ----------------
__device__ bf16 g_xn [BATCH * CK * AREA];                 // 16 MB  xn  [b][c][a]
__device__ bf16 g_xnT[BATCH * AREA * CK];                 // 16 MB  xnT [b][a][c]
__device__ bf16 g_qT [BATCH * AREA * CK];                 // 16 MB  qT  [b][a][c]
__device__ bf16 g_kT [BATCH * AREA * CK];                 // 16 MB  kT  [b][a][c]
__device__ bf16 g_v  [BATCH * CK * AREA];                 // 16 MB  v   [b][c][a]
__device__ bf16 g_OT [BATCH * AREA * CK];                 // 16 MB  OT  [b][a][c]
__device__ bf16 g_S  [(size_t)BATCH * AREA * AREA];       // 128 MB attn logits/probs
__device__ bf16 g_wb [4 * CK * CK];                       // 2 MB   wq,wk,wv,wo in bf16

// ---------------- fp32 -> bf16 weight convert ----------------
__global__ void cvt_kernel(const float* __restrict__ s, bf16* __restrict__ d, int n) {
    int i = blockIdx.x * blockDim.x + threadIdx.x;
    if (i < n) d[i] = __float2bfloat16(s[i]);
}

// ---------------- GroupNorm (fp32 in, bf16 out) ----------------
__global__ void groupnorm_kernel(const float* __restrict__ net,
                                 const float* __restrict__ scale,
                                 const float* __restrict__ bias,
                                 bf16* __restrict__ out) {
    const int grp = blockIdx.x;                 // b*GROUPS + g
    const int nelem = CPG * AREA;               // 65536
    const float* src = net + (size_t)grp * nelem;
    bf16* dst = out + (size_t)grp * nelem;

    float s = 0.f, ss = 0.f;
    for (int i = threadIdx.x; i < nelem; i += blockDim.x) {
        float x = src[i];
        s += x; ss += x * x;
    }
    __shared__ float red[64];
    #pragma unroll
    for (int o = 16; o; o >>= 1) {
        s  += __shfl_xor_sync(0xffffffffu, s,  o);
        ss += __shfl_xor_sync(0xffffffffu, ss, o);
    }
    int wid = threadIdx.x >> 5, lid = threadIdx.x & 31;
    if (lid == 0) { red[wid] = s; red[wid + 32] = ss; }
    __syncthreads();
    if (wid == 0) {
        int nw = blockDim.x >> 5;
        s  = (lid < nw) ? red[lid] : 0.f;
        ss = (lid < nw) ? red[lid + 32] : 0.f;
        #pragma unroll
        for (int o = 16; o; o >>= 1) {
            s  += __shfl_xor_sync(0xffffffffu, s,  o);
            ss += __shfl_xor_sync(0xffffffffu, ss, o);
        }
        if (lid == 0) { red[0] = s; red[1] = ss; }
    }
    __syncthreads();
    const float inv_n = 1.f / (float)nelem;
    float mean = red[0] * inv_n;
    float var  = red[1] * inv_n - mean * mean;
    float rs   = rsqrtf(var + 1e-6f);
    int g = grp & (GROUPS - 1);

    for (int i = threadIdx.x; i < nelem; i += blockDim.x) {
        int cl = i >> 12;
        int c  = g * CPG + cl;
        dst[i] = __float2bfloat16((src[i] - mean) * rs * scale[c] + bias[c]);
    }
}

// ---------------- bf16 transpose [C][A] -> [A][C], per batch z ----------------
__global__ void transpose_kernel(const bf16* __restrict__ src, bf16* __restrict__ dst) {
    __shared__ bf16 t[32][33];
    const bf16* s = src + (size_t)blockIdx.z * CK * AREA;
    bf16* d = dst + (size_t)blockIdx.z * AREA * CK;
    int a0 = blockIdx.x * 32, c0 = blockIdx.y * 32;
    for (int j = threadIdx.y; j < 32; j += 8)
        t[j][threadIdx.x] = s[(size_t)(c0 + j) * AREA + a0 + threadIdx.x];
    __syncthreads();
    for (int j = threadIdx.y; j < 32; j += 8)
        d[(size_t)(a0 + j) * CK + c0 + threadIdx.x] = t[threadIdx.x][j];
}

// ---------------- Row softmax over 4096 bf16 (in place, fp32 math) ----------------
__global__ void softmax_kernel(bf16* __restrict__ p) {
    bf16* r = p + (size_t)blockIdx.x * AREA;
    const int t = threadIdx.x;                  // 256 threads, 16 elems each
    float v[16];
    float mx = -1e30f;
    #pragma unroll
    for (int j = 0; j < 16; j++) {
        v[j] = __bfloat162float(r[t + j * 256]);
        mx = fmaxf(mx, v[j]);
    }
    __shared__ float red[8];
    #pragma unroll
    for (int o = 16; o; o >>= 1) mx = fmaxf(mx, __shfl_xor_sync(0xffffffffu, mx, o));
    int wid = t >> 5, lid = t & 31;
    if (lid == 0) red[wid] = mx;
    __syncthreads();
    mx = red[lid & 7];
    #pragma unroll
    for (int o = 4; o; o >>= 1) mx = fmaxf(mx, __shfl_xor_sync(0xffffffffu, mx, o));

    float sum = 0.f;
    #pragma unroll
    for (int j = 0; j < 16; j++) { v[j] = __expf(v[j] - mx); sum += v[j]; }
    #pragma unroll
    for (int o = 16; o; o >>= 1) sum += __shfl_xor_sync(0xffffffffu, sum, o);
    if (lid == 0) red[wid] = sum;
    __syncthreads();
    sum = red[lid & 7];
    #pragma unroll
    for (int o = 4; o; o >>= 1) sum += __shfl_xor_sync(0xffffffffu, sum, o);

    float inv = 1.f / sum;
    #pragma unroll
    for (int j = 0; j < 16; j++) r[t + j * 256] = __float2bfloat16(v[j] * inv);
}

// ---------------- bf16 tensor-core GEMM ----------------
// C[b](128-tiled M x N) = alpha * A[b] * B[b]^T  (+bias) (+res)
// A: [M][K] row-major bf16 (k contiguous), B: [N][K] row-major bf16 (k contiguous)
// BIAS_MODE: 0 none, 1 per-m, 2 per-n.  OUT_BF16: bf16 vs fp32 output.
#define LDKE 40   // padded smem row length (bf16 elems)
#define LDKW 20   // same in 32-bit words

__device__ __forceinline__ void cp_async16(void* sm, const void* gm) {
    unsigned a = (unsigned)__cvta_generic_to_shared(sm);
    asm volatile("cp.async.ca.shared.global [%0], [%1], 16;" :: "r"(a), "l"(gm));
}

template<int BIAS_MODE, int OUT_BF16, int HAS_RES>
__global__ void __launch_bounds__(256)
gemm_bf16(const bf16* __restrict__ A, size_t sA, int lda,
          const bf16* __restrict__ B, size_t sB, int ldb,
          void* __restrict__ Cv, size_t sC, int ldc,
          int K, float alpha, const float* __restrict__ bias,
          const float* __restrict__ res, size_t sR)
{
    __shared__ bf16 As[2][128 * LDKE];
    __shared__ bf16 Bs[2][128 * LDKE];

    const int bz = blockIdx.z;
    A += sA * bz; B += sB * bz;
    const int m0 = blockIdx.y * 128, n0 = blockIdx.x * 128;
    const int tid = threadIdx.x;
    const int wid = tid >> 5, lane = tid & 31;
    const int lq = lane >> 2, lr = lane & 3;
    const int wm = (wid & 1) * 64, wn = (wid >> 1) * 32;

    const int crow = tid >> 2;            // 0..63
    const int ckk  = (tid & 3) * 8;       // 0,8,16,24
    const bf16* Ag = A + (size_t)(m0 + crow) * lda + ckk;
    const bf16* Bg = B + (size_t)(n0 + crow) * ldb + ckk;

    float acc[4][4][4];
    #pragma unroll
    for (int i = 0; i < 4; i++)
        #pragma unroll
        for (int j = 0; j < 4; j++)
            #pragma unroll
            for (int r = 0; r < 4; r++) acc[i][j][r] = 0.f;

    const int nt = K >> 5;

    // prologue: stage 0
    cp_async16(&As[0][crow * LDKE + ckk], Ag);
    cp_async16(&As[0][(crow + 64) * LDKE + ckk], Ag + (size_t)64 * lda);
    cp_async16(&Bs[0][crow * LDKE + ckk], Bg);
    cp_async16(&Bs[0][(crow + 64) * LDKE + ckk], Bg + (size_t)64 * ldb);
    asm volatile("cp.async.commit_group;");

    for (int t = 0; t < nt; t++) {
        if (t + 1 < nt) {
            int s = (t + 1) & 1;
            const bf16* Ag2 = Ag + (size_t)(t + 1) * 32;
            const bf16* Bg2 = Bg + (size_t)(t + 1) * 32;
            cp_async16(&As[s][crow * LDKE + ckk], Ag2);
            cp_async16(&As[s][(crow + 64) * LDKE + ckk], Ag2 + (size_t)64 * lda);
            cp_async16(&Bs[s][crow * LDKE + ckk], Bg2);
            cp_async16(&Bs[s][(crow + 64) * LDKE + ckk], Bg2 + (size_t)64 * ldb);
            asm volatile("cp.async.commit_group;");
            asm volatile("cp.async.wait_group 1;");
        } else {
            asm volatile("cp.async.wait_group 0;");
        }
        __syncthreads();

        const uint32_t* as = (const uint32_t*)&As[t & 1][0];
        const uint32_t* bs = (const uint32_t*)&Bs[t & 1][0];

        #pragma unroll
        for (int ks = 0; ks < 2; ks++) {
            const int ko = ks * 8;
            uint32_t af[4][4], bfr[4][2];
            #pragma unroll
            for (int mt = 0; mt < 4; mt++) {
                int r = wm + mt * 16 + lq;
                af[mt][0] = as[(size_t)r * LDKW + ko + lr];
                af[mt][1] = as[(size_t)(r + 8) * LDKW + ko + lr];
                af[mt][2] = as[(size_t)r * LDKW + ko + lr + 4];
                af[mt][3] = as[(size_t)(r + 8) * LDKW + ko + lr + 4];
            }
            #pragma unroll
            for (int nn = 0; nn < 4; nn++) {
                int n = wn + nn * 8 + lq;
                bfr[nn][0] = bs[(size_t)n * LDKW + ko + lr];
                bfr[nn][1] = bs[(size_t)n * LDKW + ko + lr + 4];
            }
            #pragma unroll
            for (int mt = 0; mt < 4; mt++)
                #pragma unroll
                for (int nn = 0; nn < 4; nn++)
                    asm volatile(
                        "mma.sync.aligned.m16n8k16.row.col.f32.bf16.bf16.f32 "
                        "{%0,%1,%2,%3}, {%4,%5,%6,%7}, {%8,%9}, {%0,%1,%2,%3};"
                        : "+f"(acc[mt][nn][0]), "+f"(acc[mt][nn][1]),
                          "+f"(acc[mt][nn][2]), "+f"(acc[mt][nn][3])
                        : "r"(af[mt][0]), "r"(af[mt][1]), "r"(af[mt][2]), "r"(af[mt][3]),
                          "r"(bfr[nn][0]), "r"(bfr[nn][1]));
        }
        __syncthreads();
    }

    // epilogue
    float* Cf = (float*)Cv;
    bf16*  Cb = (bf16*)Cv;
    const size_t cbase = sC * bz;
    if (HAS_RES) res += sR * bz;

    #pragma unroll
    for (int mt = 0; mt < 4; mt++) {
        #pragma unroll
        for (int half = 0; half < 2; half++) {
            int m = m0 + wm + mt * 16 + lq + half * 8;
            float bm = (BIAS_MODE == 1) ? bias[m] : 0.f;
            #pragma unroll
            for (int nn = 0; nn < 4; nn++) {
                int n = n0 + wn + nn * 8 + 2 * lr;
                float c0 = acc[mt][nn][half * 2 + 0] * alpha;
                float c1 = acc[mt][nn][half * 2 + 1] * alpha;
                if (BIAS_MODE == 1) { c0 += bm; c1 += bm; }
                if (BIAS_MODE == 2) { c0 += bias[n]; c1 += bias[n + 1]; }
                if (OUT_BF16) {
                    __nv_bfloat162 p2;
                    p2.x = __float2bfloat16(c0);
                    p2.y = __float2bfloat16(c1);
                    *(__nv_bfloat162*)(Cb + cbase + (size_t)m * ldc + n) = p2;
                } else {
                    if (HAS_RES) {
                        c0 += res[(size_t)m * ldc + n];
                        c1 += res[(size_t)m * ldc + n + 1];
                    }
                    *(float2*)(Cf + cbase + (size_t)m * ldc + n) = make_float2(c0, c1);
                }
            }
        }
    }
}

// ---------------- launch ----------------
extern "C" void kernel_launch(void* const* d_in, const int* in_sizes, int n_in,
                              void* d_out, int out_size) {
    const float* net = (const float*)d_in[0];
    const float* gsc = (const float*)d_in[1];
    const float* gbi = (const float*)d_in[2];
    const float* wq  = (const float*)d_in[3];
    const float* bq  = (const float*)d_in[4];
    const float* wk  = (const float*)d_in[5];
    const float* bk  = (const float*)d_in[6];
    const float* wv  = (const float*)d_in[7];
    const float* bv  = (const float*)d_in[8];
    const float* wo  = (const float*)d_in[9];
    const float* bo  = (const float*)d_in[10];
    float* out = (float*)d_out;

    bf16 *xn, *xnT, *qT, *kT, *v, *OT, *S, *wb;
    cudaGetSymbolAddress((void**)&xn,  g_xn);
    cudaGetSymbolAddress((void**)&xnT, g_xnT);
    cudaGetSymbolAddress((void**)&qT,  g_qT);
    cudaGetSymbolAddress((void**)&kT,  g_kT);
    cudaGetSymbolAddress((void**)&v,   g_v);
    cudaGetSymbolAddress((void**)&OT,  g_OT);
    cudaGetSymbolAddress((void**)&S,   g_S);
    cudaGetSymbolAddress((void**)&wb,  g_wb);

    const size_t sAC = (size_t)AREA * CK;     // 2M elems (per-batch feature stride)
    const size_t sSS = (size_t)AREA * AREA;   // 16M elems (per-batch attn stride)
    const float attn_scale = 0.04419417382415922f;   // 512^-0.5

    // weights -> bf16
    cvt_kernel<<<(CK * CK + 255) / 256, 256>>>(wq, wb + 0 * CK * CK, CK * CK);
    cvt_kernel<<<(CK * CK + 255) / 256, 256>>>(wk, wb + 1 * CK * CK, CK * CK);
    cvt_kernel<<<(CK * CK + 255) / 256, 256>>>(wv, wb + 2 * CK * CK, CK * CK);
    cvt_kernel<<<(CK * CK + 255) / 256, 256>>>(wo, wb + 3 * CK * CK, CK * CK);

    groupnorm_kernel<<<BATCH * GROUPS, 512>>>(net, gsc, gbi, xn);
    transpose_kernel<<<dim3(AREA / 32, CK / 32, BATCH), dim3(32, 8)>>>(xn, xnT);

    dim3 blk(256);
    // qT[a][c] = sum_k xnT[a][k] * wq[c][k] + bq[c]   (M=AREA, N=CK)
    gemm_bf16<2, 1, 0><<<dim3(CK / 128, AREA / 128, BATCH), blk>>>(
        xnT, sAC, CK,  wb + 0 * CK * CK, 0, CK,  qT, sAC, CK, CK, 1.f, bq, nullptr, 0);
    gemm_bf16<2, 1, 0><<<dim3(CK / 128, AREA / 128, BATCH), blk>>>(
        xnT, sAC, CK,  wb + 1 * CK * CK, 0, CK,  kT, sAC, CK, CK, 1.f, bk, nullptr, 0);
    // v[c][a] = sum_k wv[c][k] * xnT[a][k] + bv[c]    (M=CK, N=AREA)
    gemm_bf16<1, 1, 0><<<dim3(AREA / 128, CK / 128, BATCH), blk>>>(
        wb + 2 * CK * CK, 0, CK,  xnT, sAC, CK,  v, (size_t)CK * AREA, AREA, CK, 1.f, bv, nullptr, 0);
    // S[i][j] = scale * sum_c qT[i][c] * kT[j][c]     (M=N=AREA, K=CK)
    gemm_bf16<0, 1, 0><<<dim3(AREA / 128, AREA / 128, BATCH), blk>>>(
        qT, sAC, CK,  kT, sAC, CK,  S, sSS, AREA, CK, attn_scale, nullptr, nullptr, 0);

    softmax_kernel<<<BATCH * AREA, 256>>>(S);

    // OT[i][c] = sum_j P[i][j] * v[c][j]              (M=AREA, N=CK, K=AREA)
    gemm_bf16<0, 1, 0><<<dim3(CK / 128, AREA / 128, BATCH), blk>>>(
        S, sSS, AREA,  v, (size_t)CK * AREA, AREA,  OT, sAC, CK, AREA, 1.f, nullptr, nullptr, 0);
    // out[o][a] = sum_c wo[o][c] * OT[a][c] + bo[o] + net[o][a]  (M=CK, N=AREA)
    gemm_bf16<1, 0, 1><<<dim3(AREA / 128, CK / 128, BATCH), blk>>>(
        wb + 3 * CK * CK, 0, CK,  OT, sAC, CK,  out, (size_t)CK * AREA, AREA, CK, 1.f, bo,
        net, (size_t)CK * AREA);
}

// round 6
// speedup vs baseline: 5.2953x; 1.1435x over previous
#include <cuda_runtime.h>
#include <cuda_bf16.h>
#include <math.h>
#include <stdint.h>

#define BATCH 4
#define CK    512
#define AREA  4096
#define GROUPS 32
#define CPG   16

typedef __nv_bfloat16 bf16;

// ---------------- scratch (device globals; no allocation) ----------------
__device__ bf16 g_xn [BATCH * CK * AREA];                 // 16 MB  xn  [b][c][a]
__device__ bf16 g_xnT[BATCH * AREA * CK];                 // 16 MB  xnT [b][a][c]
__device__ bf16 g_qT [BATCH * AREA * CK];                 // 16 MB
__device__ bf16 g_kT [BATCH * AREA * CK];                 // 16 MB
__device__ bf16 g_v  [BATCH * CK * AREA];                 // 16 MB
__device__ bf16 g_OT [BATCH * AREA * CK];                 // 16 MB
__device__ bf16 g_S  [(size_t)BATCH * AREA * AREA];       // 128 MB
__device__ bf16 g_wb [4 * CK * CK];                       // 2 MB

// ---------------- weight convert: all four in one launch ----------------
__global__ void cvt4_kernel(const float* __restrict__ w0, const float* __restrict__ w1,
                            const float* __restrict__ w2, const float* __restrict__ w3,
                            bf16* __restrict__ d) {
    int i = blockIdx.x * blockDim.x + threadIdx.x;     // 0 .. 4*CK*CK-1
    int sel = i >> 18;                                 // CK*CK = 2^18
    int off = i & ((CK * CK) - 1);
    const float* s = (sel == 0) ? w0 : (sel == 1) ? w1 : (sel == 2) ? w2 : w3;
    d[i] = __float2bfloat16(s[off]);
}

// ---------------- GroupNorm (fp32 in, bf16 out) ----------------
__global__ void groupnorm_kernel(const float* __restrict__ net,
                                 const float* __restrict__ scale,
                                 const float* __restrict__ bias,
                                 bf16* __restrict__ out) {
    const int grp = blockIdx.x;
    const int nelem = CPG * AREA;               // 65536
    const float* src = net + (size_t)grp * nelem;
    bf16* dst = out + (size_t)grp * nelem;

    float s = 0.f, ss = 0.f;
    for (int i = threadIdx.x; i < nelem; i += blockDim.x) {
        float x = src[i];
        s += x; ss += x * x;
    }
    __shared__ float red[64];
    #pragma unroll
    for (int o = 16; o; o >>= 1) {
        s  += __shfl_xor_sync(0xffffffffu, s,  o);
        ss += __shfl_xor_sync(0xffffffffu, ss, o);
    }
    int wid = threadIdx.x >> 5, lid = threadIdx.x & 31;
    if (lid == 0) { red[wid] = s; red[wid + 32] = ss; }
    __syncthreads();
    if (wid == 0) {
        int nw = blockDim.x >> 5;
        s  = (lid < nw) ? red[lid] : 0.f;
        ss = (lid < nw) ? red[lid + 32] : 0.f;
        #pragma unroll
        for (int o = 16; o; o >>= 1) {
            s  += __shfl_xor_sync(0xffffffffu, s,  o);
            ss += __shfl_xor_sync(0xffffffffu, ss, o);
        }
        if (lid == 0) { red[0] = s; red[1] = ss; }
    }
    __syncthreads();
    const float inv_n = 1.f / (float)nelem;
    float mean = red[0] * inv_n;
    float var  = red[1] * inv_n - mean * mean;
    float rs   = rsqrtf(var + 1e-6f);
    int g = grp & (GROUPS - 1);
    for (int i = threadIdx.x; i < nelem; i += blockDim.x) {
        int c = g * CPG + (i >> 12);
        dst[i] = __float2bfloat16((src[i] - mean) * rs * scale[c] + bias[c]);
    }
}

// ---------------- bf16 transpose [C][A] -> [A][C], per batch z ----------------
__global__ void transpose_kernel(const bf16* __restrict__ src, bf16* __restrict__ dst) {
    __shared__ bf16 t[32][33];
    const bf16* s = src + (size_t)blockIdx.z * CK * AREA;
    bf16* d = dst + (size_t)blockIdx.z * AREA * CK;
    int a0 = blockIdx.x * 32, c0 = blockIdx.y * 32;
    for (int j = threadIdx.y; j < 32; j += 8)
        t[j][threadIdx.x] = s[(size_t)(c0 + j) * AREA + a0 + threadIdx.x];
    __syncthreads();
    for (int j = threadIdx.y; j < 32; j += 8)
        d[(size_t)(a0 + j) * CK + c0 + threadIdx.x] = t[threadIdx.x][j];
}

// ---------------- Row softmax over 4096 bf16 (in place, fp32 math) ----------------
__global__ void softmax_kernel(bf16* __restrict__ p) {
    bf16* r = p + (size_t)blockIdx.x * AREA;
    const int t = threadIdx.x;
    float v[16];
    float mx = -1e30f;
    #pragma unroll
    for (int j = 0; j < 16; j++) {
        v[j] = __bfloat162float(r[t + j * 256]);
        mx = fmaxf(mx, v[j]);
    }
    __shared__ float red[8];
    #pragma unroll
    for (int o = 16; o; o >>= 1) mx = fmaxf(mx, __shfl_xor_sync(0xffffffffu, mx, o));
    int wid = t >> 5, lid = t & 31;
    if (lid == 0) red[wid] = mx;
    __syncthreads();
    mx = red[lid & 7];
    #pragma unroll
    for (int o = 4; o; o >>= 1) mx = fmaxf(mx, __shfl_xor_sync(0xffffffffu, mx, o));
    float sum = 0.f;
    #pragma unroll
    for (int j = 0; j < 16; j++) { v[j] = __expf(v[j] - mx); sum += v[j]; }
    #pragma unroll
    for (int o = 16; o; o >>= 1) sum += __shfl_xor_sync(0xffffffffu, sum, o);
    if (lid == 0) red[wid] = sum;
    __syncthreads();
    sum = red[lid & 7];
    #pragma unroll
    for (int o = 4; o; o >>= 1) sum += __shfl_xor_sync(0xffffffffu, sum, o);
    float inv = 1.f / sum;
    #pragma unroll
    for (int j = 0; j < 16; j++) r[t + j * 256] = __float2bfloat16(v[j] * inv);
}

// ---------------- bf16 tensor-core GEMM (mma.sync + ldmatrix + 3-stage) ----------------
// C[b](128x128 tiles) = alpha * A[b] * B[b]^T  (+bias) (+res)
// A: [M][K] bf16 K-contig, B: [N][K] bf16 K-contig.
// BIAS_MODE: 0 none, 1 per-m, 2 per-n.  OUT_BF16: bf16 vs fp32 out.

#define LDKE 40                         // padded smem row (bf16 elems) -> conflict-free
#define KCH  32                         // K per stage
#define NST  3                          // pipeline stages
#define MAT_BYTES (128 * LDKE * 2)      // 10240 B per matrix per stage
#define SMEM_GEMM (NST * 2 * MAT_BYTES) // 61440 B

__device__ __forceinline__ void cpa16(uint32_t sm, const void* gm) {
    asm volatile("cp.async.ca.shared.global [%0], [%1], 16;" :: "r"(sm), "l"(gm));
}
__device__ __forceinline__ void ldm_x4(uint32_t& r0, uint32_t& r1, uint32_t& r2,
                                       uint32_t& r3, uint32_t addr) {
    asm volatile("ldmatrix.sync.aligned.m8n8.x4.shared.b16 {%0,%1,%2,%3}, [%4];"
                 : "=r"(r0), "=r"(r1), "=r"(r2), "=r"(r3) : "r"(addr));
}

template<int BIAS_MODE, int OUT_BF16, int HAS_RES>
__global__ void __launch_bounds__(256, 2)
gemm_bf16(const bf16* __restrict__ A, size_t sA, int lda,
          const bf16* __restrict__ B, size_t sB, int ldb,
          void* __restrict__ Cv, size_t sC, int ldc,
          int K, float alpha, const float* __restrict__ bias,
          const float* __restrict__ res, size_t sR)
{
    extern __shared__ bf16 sm[];
    uint32_t smb;
    asm("{ .reg .u64 t; cvta.to.shared.u64 t, %1; cvt.u32.u64 %0, t; }"
        : "=r"(smb) : "l"(sm));
    // byte offsets: A stages at 0, B stages after
    const uint32_t BOFF = NST * MAT_BYTES;

    const int bz = blockIdx.z;
    A += sA * bz; B += sB * bz;
    const int m0 = blockIdx.y * 128, n0 = blockIdx.x * 128;
    const int tid = threadIdx.x;
    const int wid = tid >> 5, lane = tid & 31;
    const int wm = (wid & 1) * 64, wn = (wid >> 1) * 32;
    const int sel = lane >> 3, l7 = lane & 7;

    // ldmatrix per-lane address parts (bf16-elem units)
    const uint32_t aLane = (uint32_t)(((sel & 1) * 8 + l7) * LDKE + ((sel & 2) ? 8 : 0));
    const uint32_t bLane = (uint32_t)((((sel & 2) ? 8 : 0) + l7) * LDKE + ((sel & 1) ? 8 : 0));

    // cp.async staging coords
    const int crow = tid >> 2;            // 0..63
    const int ckk  = (tid & 3) * 8;       // 0,8,16,24
    const bf16* Ag = A + (size_t)(m0 + crow) * lda + ckk;
    const bf16* Bg = B + (size_t)(n0 + crow) * ldb + ckk;
    const uint32_t dElem = (uint32_t)(crow * LDKE + ckk);
    const uint32_t dElem64 = (uint32_t)((crow + 64) * LDKE + ckk);

    float acc[4][4][4];
    #pragma unroll
    for (int i = 0; i < 4; i++)
        #pragma unroll
        for (int j = 0; j < 4; j++)
            #pragma unroll
            for (int r = 0; r < 4; r++) acc[i][j][r] = 0.f;

    const int nt = K / KCH;

    // stage s <- chunk t
    auto stage = [&](int s, int t) {
        const bf16* Ags = Ag + (size_t)t * KCH;
        const bf16* Bgs = Bg + (size_t)t * KCH;
        uint32_t sa = smb + (uint32_t)s * MAT_BYTES;
        uint32_t sb = smb + BOFF + (uint32_t)s * MAT_BYTES;
        cpa16(sa + dElem * 2, Ags);
        cpa16(sa + dElem64 * 2, Ags + (size_t)64 * lda);
        cpa16(sb + dElem * 2, Bgs);
        cpa16(sb + dElem64 * 2, Bgs + (size_t)64 * ldb);
        asm volatile("cp.async.commit_group;");
    };

    stage(0, 0);
    stage(1, 1);

    int s = 0;
    for (int t = 0; t < nt; t++) {
        if (t + 1 < nt) asm volatile("cp.async.wait_group 1;");
        else            asm volatile("cp.async.wait_group 0;");
        __syncthreads();

        if (t + 2 < nt) stage((t + 2) % NST, t + 2);

        const uint32_t sa = smb + (uint32_t)s * MAT_BYTES;
        const uint32_t sb = smb + BOFF + (uint32_t)s * MAT_BYTES;

        #pragma unroll
        for (int ks = 0; ks < 2; ks++) {
            uint32_t af[4][4], bfr[4][2];
            #pragma unroll
            for (int mt = 0; mt < 4; mt++) {
                uint32_t addr = sa + 2 * ((uint32_t)((wm + mt * 16) * LDKE) + aLane)
                              + (uint32_t)ks * 32;
                ldm_x4(af[mt][0], af[mt][1], af[mt][2], af[mt][3], addr);
            }
            #pragma unroll
            for (int p = 0; p < 2; p++) {
                uint32_t addr = sb + 2 * ((uint32_t)((wn + p * 16) * LDKE) + bLane)
                              + (uint32_t)ks * 32;
                ldm_x4(bfr[2 * p][0], bfr[2 * p][1], bfr[2 * p + 1][0], bfr[2 * p + 1][1], addr);
            }
            #pragma unroll
            for (int mt = 0; mt < 4; mt++)
                #pragma unroll
                for (int nn = 0; nn < 4; nn++)
                    asm volatile(
                        "mma.sync.aligned.m16n8k16.row.col.f32.bf16.bf16.f32 "
                        "{%0,%1,%2,%3}, {%4,%5,%6,%7}, {%8,%9}, {%0,%1,%2,%3};"
                        : "+f"(acc[mt][nn][0]), "+f"(acc[mt][nn][1]),
                          "+f"(acc[mt][nn][2]), "+f"(acc[mt][nn][3])
                        : "r"(af[mt][0]), "r"(af[mt][1]), "r"(af[mt][2]), "r"(af[mt][3]),
                          "r"(bfr[nn][0]), "r"(bfr[nn][1]));
        }
        __syncthreads();
        s = (s + 1 == NST) ? 0 : s + 1;
    }

    // epilogue
    const int lq = lane >> 2, lr = lane & 3;
    float* Cf = (float*)Cv;
    bf16*  Cb = (bf16*)Cv;
    const size_t cbase = sC * bz;
    if (HAS_RES) res += sR * bz;

    #pragma unroll
    for (int mt = 0; mt < 4; mt++) {
        #pragma unroll
        for (int half = 0; half < 2; half++) {
            int m = m0 + wm + mt * 16 + lq + half * 8;
            float bm = (BIAS_MODE == 1) ? bias[m] : 0.f;
            #pragma unroll
            for (int nn = 0; nn < 4; nn++) {
                int n = n0 + wn + nn * 8 + 2 * lr;
                float c0 = acc[mt][nn][half * 2 + 0] * alpha;
                float c1 = acc[mt][nn][half * 2 + 1] * alpha;
                if (BIAS_MODE == 1) { c0 += bm; c1 += bm; }
                if (BIAS_MODE == 2) { c0 += bias[n]; c1 += bias[n + 1]; }
                if (OUT_BF16) {
                    __nv_bfloat162 p2;
                    p2.x = __float2bfloat16(c0);
                    p2.y = __float2bfloat16(c1);
                    *(__nv_bfloat162*)(Cb + cbase + (size_t)m * ldc + n) = p2;
                } else {
                    if (HAS_RES) {
                        c0 += res[(size_t)m * ldc + n];
                        c1 += res[(size_t)m * ldc + n + 1];
                    }
                    *(float2*)(Cf + cbase + (size_t)m * ldc + n) = make_float2(c0, c1);
                }
            }
        }
    }
}

// ---------------- launch ----------------
extern "C" void kernel_launch(void* const* d_in, const int* in_sizes, int n_in,
                              void* d_out, int out_size) {
    const float* net = (const float*)d_in[0];
    const float* gsc = (const float*)d_in[1];
    const float* gbi = (const float*)d_in[2];
    const float* wq  = (const float*)d_in[3];
    const float* bq  = (const float*)d_in[4];
    const float* wk  = (const float*)d_in[5];
    const float* bk  = (const float*)d_in[6];
    const float* wv  = (const float*)d_in[7];
    const float* bv  = (const float*)d_in[8];
    const float* wo  = (const float*)d_in[9];
    const float* bo  = (const float*)d_in[10];
    float* out = (float*)d_out;

    bf16 *xn, *xnT, *qT, *kT, *v, *OT, *S, *wb;
    cudaGetSymbolAddress((void**)&xn,  g_xn);
    cudaGetSymbolAddress((void**)&xnT, g_xnT);
    cudaGetSymbolAddress((void**)&qT,  g_qT);
    cudaGetSymbolAddress((void**)&kT,  g_kT);
    cudaGetSymbolAddress((void**)&v,   g_v);
    cudaGetSymbolAddress((void**)&OT,  g_OT);
    cudaGetSymbolAddress((void**)&S,   g_S);
    cudaGetSymbolAddress((void**)&wb,  g_wb);

    cudaFuncSetAttribute(gemm_bf16<2,1,0>, cudaFuncAttributeMaxDynamicSharedMemorySize, SMEM_GEMM);
    cudaFuncSetAttribute(gemm_bf16<1,1,0>, cudaFuncAttributeMaxDynamicSharedMemorySize, SMEM_GEMM);
    cudaFuncSetAttribute(gemm_bf16<0,1,0>, cudaFuncAttributeMaxDynamicSharedMemorySize, SMEM_GEMM);
    cudaFuncSetAttribute(gemm_bf16<1,0,1>, cudaFuncAttributeMaxDynamicSharedMemorySize, SMEM_GEMM);

    const size_t sAC = (size_t)AREA * CK;
    const size_t sCA = (size_t)CK * AREA;
    const size_t sSS = (size_t)AREA * AREA;
    const float attn_scale = 0.04419417382415922f;   // 512^-0.5

    cvt4_kernel<<<(4 * CK * CK) / 256, 256>>>(wq, wk, wv, wo, wb);
    groupnorm_kernel<<<BATCH * GROUPS, 512>>>(net, gsc, gbi, xn);
    transpose_kernel<<<dim3(AREA / 32, CK / 32, BATCH), dim3(32, 8)>>>(xn, xnT);

    dim3 blk(256);
    dim3 grdQK(CK / 128, AREA / 128, BATCH);
    dim3 grdV (AREA / 128, CK / 128, BATCH);
    dim3 grdS (AREA / 128, AREA / 128, BATCH);

    // qT[a][c] = xnT[a][:] . wq[c][:] + bq[c]
    gemm_bf16<2,1,0><<<grdQK, blk, SMEM_GEMM>>>(
        xnT, sAC, CK,  wb + 0 * CK * CK, 0, CK,  qT, sAC, CK, CK, 1.f, bq, nullptr, 0);
    gemm_bf16<2,1,0><<<grdQK, blk, SMEM_GEMM>>>(
        xnT, sAC, CK,  wb + 1 * CK * CK, 0, CK,  kT, sAC, CK, CK, 1.f, bk, nullptr, 0);
    // v[c][a] = wv[c][:] . xnT[a][:] + bv[c]
    gemm_bf16<1,1,0><<<grdV, blk, SMEM_GEMM>>>(
        wb + 2 * CK * CK, 0, CK,  xnT, sAC, CK,  v, sCA, AREA, CK, 1.f, bv, nullptr, 0);
    // S[i][j] = scale * qT[i][:] . kT[j][:]
    gemm_bf16<0,1,0><<<grdS, blk, SMEM_GEMM>>>(
        qT, sAC, CK,  kT, sAC, CK,  S, sSS, AREA, CK, attn_scale, nullptr, nullptr, 0);

    softmax_kernel<<<BATCH * AREA, 256>>>(S);

    // OT[i][c] = P[i][:] . v[c][:]
    gemm_bf16<0,1,0><<<grdQK, blk, SMEM_GEMM>>>(
        S, sSS, AREA,  v, sCA, AREA,  OT, sAC, CK, AREA, 1.f, nullptr, nullptr, 0);
    // out[o][a] = wo[o][:] . OT[a][:] + bo[o] + net[o][a]
    gemm_bf16<1,0,1><<<grdV, blk, SMEM_GEMM>>>(
        wb + 3 * CK * CK, 0, CK,  OT, sAC, CK,  out, sCA, AREA, CK, 1.f, bo, net, sCA);
}

// round 7
// speedup vs baseline: 5.3387x; 1.0082x over previous
#include <cuda_runtime.h>
#include <cuda_bf16.h>
#include <math.h>
#include <stdint.h>

#define BATCH 4
#define CK    512
#define AREA  4096
#define GROUPS 32
#define CPG   16

typedef __nv_bfloat16 bf16;

// ---------------- scratch (device globals; no allocation) ----------------
__device__ bf16 g_xn [BATCH * CK * AREA];                 // 16 MB  xn  [b][c][a]
__device__ bf16 g_xnT[BATCH * AREA * CK];                 // 16 MB  xnT [b][a][c]
__device__ bf16 g_qT [BATCH * AREA * CK];                 // 16 MB
__device__ bf16 g_kT [BATCH * AREA * CK];                 // 16 MB
__device__ bf16 g_v  [BATCH * CK * AREA];                 // 16 MB
__device__ bf16 g_OT [BATCH * AREA * CK];                 // 16 MB
__device__ bf16 g_S  [(size_t)BATCH * AREA * AREA];       // 128 MB
__device__ bf16 g_wb [4 * CK * CK];                       // 2 MB

// ---------------- weight convert: all four in one launch ----------------
__global__ void cvt4_kernel(const float* __restrict__ w0, const float* __restrict__ w1,
                            const float* __restrict__ w2, const float* __restrict__ w3,
                            bf16* __restrict__ d) {
    int i = blockIdx.x * blockDim.x + threadIdx.x;     // 0 .. 4*CK*CK-1
    int sel = i >> 18;                                 // CK*CK = 2^18
    int off = i & ((CK * CK) - 1);
    const float* s = (sel == 0) ? w0 : (sel == 1) ? w1 : (sel == 2) ? w2 : w3;
    d[i] = __float2bfloat16(s[off]);
}

// ---------------- GroupNorm (fp32 in, bf16 out) ----------------
__global__ void groupnorm_kernel(const float* __restrict__ net,
                                 const float* __restrict__ scale,
                                 const float* __restrict__ bias,
                                 bf16* __restrict__ out) {
    const int grp = blockIdx.x;
    const int nelem = CPG * AREA;               // 65536
    const float* src = net + (size_t)grp * nelem;
    bf16* dst = out + (size_t)grp * nelem;

    float s = 0.f, ss = 0.f;
    for (int i = threadIdx.x; i < nelem; i += blockDim.x) {
        float x = src[i];
        s += x; ss += x * x;
    }
    __shared__ float red[64];
    #pragma unroll
    for (int o = 16; o; o >>= 1) {
        s  += __shfl_xor_sync(0xffffffffu, s,  o);
        ss += __shfl_xor_sync(0xffffffffu, ss, o);
    }
    int wid = threadIdx.x >> 5, lid = threadIdx.x & 31;
    if (lid == 0) { red[wid] = s; red[wid + 32] = ss; }
    __syncthreads();
    if (wid == 0) {
        int nw = blockDim.x >> 5;
        s  = (lid < nw) ? red[lid] : 0.f;
        ss = (lid < nw) ? red[lid + 32] : 0.f;
        #pragma unroll
        for (int o = 16; o; o >>= 1) {
            s  += __shfl_xor_sync(0xffffffffu, s,  o);
            ss += __shfl_xor_sync(0xffffffffu, ss, o);
        }
        if (lid == 0) { red[0] = s; red[1] = ss; }
    }
    __syncthreads();
    const float inv_n = 1.f / (float)nelem;
    float mean = red[0] * inv_n;
    float var  = red[1] * inv_n - mean * mean;
    float rs   = rsqrtf(var + 1e-6f);
    int g = grp & (GROUPS - 1);
    for (int i = threadIdx.x; i < nelem; i += blockDim.x) {
        int c = g * CPG + (i >> 12);
        dst[i] = __float2bfloat16((src[i] - mean) * rs * scale[c] + bias[c]);
    }
}

// ---------------- bf16 transpose [C][A] -> [A][C], per batch z ----------------
__global__ void transpose_kernel(const bf16* __restrict__ src, bf16* __restrict__ dst) {
    __shared__ bf16 t[32][33];
    const bf16* s = src + (size_t)blockIdx.z * CK * AREA;
    bf16* d = dst + (size_t)blockIdx.z * AREA * CK;
    int a0 = blockIdx.x * 32, c0 = blockIdx.y * 32;
    for (int j = threadIdx.y; j < 32; j += 8)
        t[j][threadIdx.x] = s[(size_t)(c0 + j) * AREA + a0 + threadIdx.x];
    __syncthreads();
    for (int j = threadIdx.y; j < 32; j += 8)
        d[(size_t)(a0 + j) * CK + c0 + threadIdx.x] = t[threadIdx.x][j];
}

// ---------------- Row softmax over 4096 bf16 (in place, fp32 math) ----------------
__global__ void softmax_kernel(bf16* __restrict__ p) {
    bf16* r = p + (size_t)blockIdx.x * AREA;
    const int t = threadIdx.x;
    float v[16];
    float mx = -1e30f;
    #pragma unroll
    for (int j = 0; j < 16; j++) {
        v[j] = __bfloat162float(r[t + j * 256]);
        mx = fmaxf(mx, v[j]);
    }
    __shared__ float red[8];
    #pragma unroll
    for (int o = 16; o; o >>= 1) mx = fmaxf(mx, __shfl_xor_sync(0xffffffffu, mx, o));
    int wid = t >> 5, lid = t & 31;
    if (lid == 0) red[wid] = mx;
    __syncthreads();
    mx = red[lid & 7];
    #pragma unroll
    for (int o = 4; o; o >>= 1) mx = fmaxf(mx, __shfl_xor_sync(0xffffffffu, mx, o));
    float sum = 0.f;
    #pragma unroll
    for (int j = 0; j < 16; j++) { v[j] = __expf(v[j] - mx); sum += v[j]; }
    #pragma unroll
    for (int o = 16; o; o >>= 1) sum += __shfl_xor_sync(0xffffffffu, sum, o);
    if (lid == 0) red[wid] = sum;
    __syncthreads();
    sum = red[lid & 7];
    #pragma unroll
    for (int o = 4; o; o >>= 1) sum += __shfl_xor_sync(0xffffffffu, sum, o);
    float inv = 1.f / sum;
    #pragma unroll
    for (int j = 0; j < 16; j++) r[t + j * 256] = __float2bfloat16(v[j] * inv);
}

// ---------------- bf16 tensor-core GEMM ----------------
// C[b](128x128 tiles) = alpha * A[b] * B[b]^T  (+bias) (+res)
// A: [M][K] bf16 K-contig, B: [N][K] bf16 K-contig.
// KCH=64, 3 stages, single __syncthreads per chunk.
// BIAS_MODE: 0 none, 1 per-m, 2 per-n.  OUT_BF16: bf16 vs fp32 out.

#define LDKE 72                         // padded smem row (64+8 bf16) -> conflict-free
#define KCH  64                         // K per stage
#define NST  3                          // pipeline stages
#define MAT_BYTES (128 * LDKE * 2)      // 18432 B per matrix per stage
#define SMEM_GEMM (NST * 2 * MAT_BYTES) // 110592 B

__device__ __forceinline__ void cpa16(uint32_t sm, const void* gm) {
    asm volatile("cp.async.ca.shared.global [%0], [%1], 16;" :: "r"(sm), "l"(gm));
}
__device__ __forceinline__ void ldm_x4(uint32_t& r0, uint32_t& r1, uint32_t& r2,
                                       uint32_t& r3, uint32_t addr) {
    asm volatile("ldmatrix.sync.aligned.m8n8.x4.shared.b16 {%0,%1,%2,%3}, [%4];"
                 : "=r"(r0), "=r"(r1), "=r"(r2), "=r"(r3) : "r"(addr));
}

template<int BIAS_MODE, int OUT_BF16, int HAS_RES>
__global__ void __launch_bounds__(256, 2)
gemm_bf16(const bf16* __restrict__ A, size_t sA, int lda,
          const bf16* __restrict__ B, size_t sB, int ldb,
          void* __restrict__ Cv, size_t sC, int ldc,
          int K, float alpha, const float* __restrict__ bias,
          const float* __restrict__ res, size_t sR)
{
    extern __shared__ bf16 sm[];
    uint32_t smb;
    asm("{ .reg .u64 t; cvta.to.shared.u64 t, %1; cvt.u32.u64 %0, t; }"
        : "=r"(smb) : "l"(sm));
    const uint32_t BOFF = NST * MAT_BYTES;

    const int bz = blockIdx.z;
    A += sA * bz; B += sB * bz;
    const int m0 = blockIdx.y * 128, n0 = blockIdx.x * 128;
    const int tid = threadIdx.x;
    const int wid = tid >> 5, lane = tid & 31;
    const int wm = (wid & 1) * 64, wn = (wid >> 1) * 32;
    const int sel = lane >> 3, l7 = lane & 7;

    // ldmatrix per-lane address parts (bf16-elem units)
    const uint32_t aLane = (uint32_t)(((sel & 1) * 8 + l7) * LDKE + ((sel & 2) ? 8 : 0));
    const uint32_t bLane = (uint32_t)((((sel & 2) ? 8 : 0) + l7) * LDKE + ((sel & 1) ? 8 : 0));

    // cp.async staging coords: 4 x 16B segments per matrix per thread
    // seg = i*256 + tid; row = seg>>3 (8 x 16B = 128 B per row), k16 = seg&7
    float acc[4][4][4];
    #pragma unroll
    for (int i = 0; i < 4; i++)
        #pragma unroll
        for (int j = 0; j < 4; j++)
            #pragma unroll
            for (int r = 0; r < 4; r++) acc[i][j][r] = 0.f;

    const bf16* Abase = A + (size_t)m0 * lda;
    const bf16* Bbase = B + (size_t)n0 * ldb;
    const int nt = K / KCH;

    auto stage = [&](int s, int t) {
        uint32_t sa = smb + (uint32_t)s * MAT_BYTES;
        uint32_t sb = smb + BOFF + (uint32_t)s * MAT_BYTES;
        const bf16* Ags = Abase + (size_t)t * KCH;
        const bf16* Bgs = Bbase + (size_t)t * KCH;
        #pragma unroll
        for (int i = 0; i < 4; i++) {
            int seg = i * 256 + tid;
            int row = seg >> 3, k16 = seg & 7;
            uint32_t off = (uint32_t)(row * (LDKE * 2) + k16 * 16);
            cpa16(sa + off, Ags + (size_t)row * lda + k16 * 8);
            cpa16(sb + off, Bgs + (size_t)row * ldb + k16 * 8);
        }
        asm volatile("cp.async.commit_group;");
    };

    stage(0, 0);
    stage(1, 1);

    int s = 0;
    for (int t = 0; t < nt; t++) {
        if (t + 1 < nt) asm volatile("cp.async.wait_group 1;");
        else            asm volatile("cp.async.wait_group 0;");
        __syncthreads();

        if (t + 2 < nt) stage((t + 2) % NST, t + 2);

        const uint32_t sa = smb + (uint32_t)s * MAT_BYTES;
        const uint32_t sb = smb + BOFF + (uint32_t)s * MAT_BYTES;

        #pragma unroll
        for (int ks = 0; ks < 4; ks++) {
            uint32_t af[4][4], bfr[4][2];
            #pragma unroll
            for (int mt = 0; mt < 4; mt++) {
                uint32_t addr = sa + 2 * ((uint32_t)((wm + mt * 16) * LDKE) + aLane)
                              + (uint32_t)ks * 32;
                ldm_x4(af[mt][0], af[mt][1], af[mt][2], af[mt][3], addr);
            }
            #pragma unroll
            for (int p = 0; p < 2; p++) {
                uint32_t addr = sb + 2 * ((uint32_t)((wn + p * 16) * LDKE) + bLane)
                              + (uint32_t)ks * 32;
                ldm_x4(bfr[2 * p][0], bfr[2 * p][1], bfr[2 * p + 1][0], bfr[2 * p + 1][1], addr);
            }
            #pragma unroll
            for (int mt = 0; mt < 4; mt++)
                #pragma unroll
                for (int nn = 0; nn < 4; nn++)
                    asm volatile(
                        "mma.sync.aligned.m16n8k16.row.col.f32.bf16.bf16.f32 "
                        "{%0,%1,%2,%3}, {%4,%5,%6,%7}, {%8,%9}, {%0,%1,%2,%3};"
                        : "+f"(acc[mt][nn][0]), "+f"(acc[mt][nn][1]),
                          "+f"(acc[mt][nn][2]), "+f"(acc[mt][nn][3])
                        : "r"(af[mt][0]), "r"(af[mt][1]), "r"(af[mt][2]), "r"(af[mt][3]),
                          "r"(bfr[nn][0]), "r"(bfr[nn][1]));
        }
        s = (s + 1 == NST) ? 0 : s + 1;
    }

    // epilogue
    const int lq = lane >> 2, lr = lane & 3;
    float* Cf = (float*)Cv;
    bf16*  Cb = (bf16*)Cv;
    const size_t cbase = sC * bz;
    if (HAS_RES) res += sR * bz;

    #pragma unroll
    for (int mt = 0; mt < 4; mt++) {
        #pragma unroll
        for (int half = 0; half < 2; half++) {
            int m = m0 + wm + mt * 16 + lq + half * 8;
            float bm = (BIAS_MODE == 1) ? bias[m] : 0.f;
            #pragma unroll
            for (int nn = 0; nn < 4; nn++) {
                int n = n0 + wn + nn * 8 + 2 * lr;
                float c0 = acc[mt][nn][half * 2 + 0] * alpha;
                float c1 = acc[mt][nn][half * 2 + 1] * alpha;
                if (BIAS_MODE == 1) { c0 += bm; c1 += bm; }
                if (BIAS_MODE == 2) { c0 += bias[n]; c1 += bias[n + 1]; }
                if (OUT_BF16) {
                    __nv_bfloat162 p2;
                    p2.x = __float2bfloat16(c0);
                    p2.y = __float2bfloat16(c1);
                    *(__nv_bfloat162*)(Cb + cbase + (size_t)m * ldc + n) = p2;
                } else {
                    if (HAS_RES) {
                        c0 += res[(size_t)m * ldc + n];
                        c1 += res[(size_t)m * ldc + n + 1];
                    }
                    *(float2*)(Cf + cbase + (size_t)m * ldc + n) = make_float2(c0, c1);
                }
            }
        }
    }
}

// ---------------- launch ----------------
extern "C" void kernel_launch(void* const* d_in, const int* in_sizes, int n_in,
                              void* d_out, int out_size) {
    const float* net = (const float*)d_in[0];
    const float* gsc = (const float*)d_in[1];
    const float* gbi = (const float*)d_in[2];
    const float* wq  = (const float*)d_in[3];
    const float* bq  = (const float*)d_in[4];
    const float* wk  = (const float*)d_in[5];
    const float* bk  = (const float*)d_in[6];
    const float* wv  = (const float*)d_in[7];
    const float* bv  = (const float*)d_in[8];
    const float* wo  = (const float*)d_in[9];
    const float* bo  = (const float*)d_in[10];
    float* out = (float*)d_out;

    bf16 *xn, *xnT, *qT, *kT, *v, *OT, *S, *wb;
    cudaGetSymbolAddress((void**)&xn,  g_xn);
    cudaGetSymbolAddress((void**)&xnT, g_xnT);
    cudaGetSymbolAddress((void**)&qT,  g_qT);
    cudaGetSymbolAddress((void**)&kT,  g_kT);
    cudaGetSymbolAddress((void**)&v,   g_v);
    cudaGetSymbolAddress((void**)&OT,  g_OT);
    cudaGetSymbolAddress((void**)&S,   g_S);
    cudaGetSymbolAddress((void**)&wb,  g_wb);

    cudaFuncSetAttribute(gemm_bf16<2,1,0>, cudaFuncAttributeMaxDynamicSharedMemorySize, SMEM_GEMM);
    cudaFuncSetAttribute(gemm_bf16<1,1,0>, cudaFuncAttributeMaxDynamicSharedMemorySize, SMEM_GEMM);
    cudaFuncSetAttribute(gemm_bf16<0,1,0>, cudaFuncAttributeMaxDynamicSharedMemorySize, SMEM_GEMM);
    cudaFuncSetAttribute(gemm_bf16<1,0,1>, cudaFuncAttributeMaxDynamicSharedMemorySize, SMEM_GEMM);

    const size_t sAC = (size_t)AREA * CK;
    const size_t sCA = (size_t)CK * AREA;
    const size_t sSS = (size_t)AREA * AREA;
    const float attn_scale = 0.04419417382415922f;   // 512^-0.5

    cvt4_kernel<<<(4 * CK * CK) / 256, 256>>>(wq, wk, wv, wo, wb);
    groupnorm_kernel<<<BATCH * GROUPS, 512>>>(net, gsc, gbi, xn);
    transpose_kernel<<<dim3(AREA / 32, CK / 32, BATCH), dim3(32, 8)>>>(xn, xnT);

    dim3 blk(256);
    dim3 grdQK(CK / 128, AREA / 128, BATCH);
    dim3 grdV (AREA / 128, CK / 128, BATCH);
    dim3 grdS (AREA / 128, AREA / 128, BATCH);

    // qT[a][c] = xnT[a][:] . wq[c][:] + bq[c]
    gemm_bf16<2,1,0><<<grdQK, blk, SMEM_GEMM>>>(
        xnT, sAC, CK,  wb + 0 * CK * CK, 0, CK,  qT, sAC, CK, CK, 1.f, bq, nullptr, 0);
    gemm_bf16<2,1,0><<<grdQK, blk, SMEM_GEMM>>>(
        xnT, sAC, CK,  wb + 1 * CK * CK, 0, CK,  kT, sAC, CK, CK, 1.f, bk, nullptr, 0);
    // v[c][a] = wv[c][:] . xnT[a][:] + bv[c]
    gemm_bf16<1,1,0><<<grdV, blk, SMEM_GEMM>>>(
        wb + 2 * CK * CK, 0, CK,  xnT, sAC, CK,  v, sCA, AREA, CK, 1.f, bv, nullptr, 0);
    // S[i][j] = scale * qT[i][:] . kT[j][:]
    gemm_bf16<0,1,0><<<grdS, blk, SMEM_GEMM>>>(
        qT, sAC, CK,  kT, sAC, CK,  S, sSS, AREA, CK, attn_scale, nullptr, nullptr, 0);

    softmax_kernel<<<BATCH * AREA, 256>>>(S);

    // OT[i][c] = P[i][:] . v[c][:]
    gemm_bf16<0,1,0><<<grdQK, blk, SMEM_GEMM>>>(
        S, sSS, AREA,  v, sCA, AREA,  OT, sAC, CK, AREA, 1.f, nullptr, nullptr, 0);
    // out[o][a] = wo[o][:] . OT[a][:] + bo[o] + net[o][a]
    gemm_bf16<1,0,1><<<grdV, blk, SMEM_GEMM>>>(
        wb + 3 * CK * CK, 0, CK,  OT, sAC, CK,  out, sCA, AREA, CK, 1.f, bo, net, sCA);
}

// round 9
// speedup vs baseline: 5.9934x; 1.1226x over previous
#include <cuda_runtime.h>
#include <cuda_bf16.h>
#include <math.h>
#include <stdint.h>

#define BATCH 4
#define CK    512
#define AREA  4096
#define GROUPS 32
#define CPG   16

typedef __nv_bfloat16 bf16;

// ---------------- scratch (device globals; no allocation) ----------------
__device__ bf16 g_xn [BATCH * CK * AREA];                 // 16 MB  xn  [b][c][a]
__device__ bf16 g_xnT[BATCH * AREA * CK];                 // 16 MB  xnT [b][a][c]
__device__ bf16 g_qT [BATCH * AREA * CK];                 // 16 MB
__device__ bf16 g_kT [BATCH * AREA * CK];                 // 16 MB
__device__ bf16 g_v  [BATCH * CK * AREA];                 // 16 MB
__device__ bf16 g_OT [BATCH * AREA * CK];                 // 16 MB
__device__ bf16 g_S  [(size_t)BATCH * AREA * AREA];       // 128 MB
__device__ bf16 g_wb [4 * CK * CK];                       // 2 MB

// ---------------- weight convert: all four in one launch ----------------
__global__ void cvt4_kernel(const float* __restrict__ w0, const float* __restrict__ w1,
                            const float* __restrict__ w2, const float* __restrict__ w3,
                            bf16* __restrict__ d) {
    int i = blockIdx.x * blockDim.x + threadIdx.x;     // 0 .. 4*CK*CK-1
    int sel = i >> 18;                                 // CK*CK = 2^18
    int off = i & ((CK * CK) - 1);
    const float* s = (sel == 0) ? w0 : (sel == 1) ? w1 : (sel == 2) ? w2 : w3;
    d[i] = __float2bfloat16(s[off]);
}

// ---------------- GroupNorm (fp32 in, bf16 out) ----------------
__global__ void groupnorm_kernel(const float* __restrict__ net,
                                 const float* __restrict__ scale,
                                 const float* __restrict__ bias,
                                 bf16* __restrict__ out) {
    const int grp = blockIdx.x;
    const int nelem = CPG * AREA;               // 65536
    const float* src = net + (size_t)grp * nelem;
    bf16* dst = out + (size_t)grp * nelem;

    float s = 0.f, ss = 0.f;
    for (int i = threadIdx.x; i < nelem; i += blockDim.x) {
        float x = src[i];
        s += x; ss += x * x;
    }
    __shared__ float red[64];
    #pragma unroll
    for (int o = 16; o; o >>= 1) {
        s  += __shfl_xor_sync(0xffffffffu, s,  o);
        ss += __shfl_xor_sync(0xffffffffu, ss, o);
    }
    int wid = threadIdx.x >> 5, lid = threadIdx.x & 31;
    if (lid == 0) { red[wid] = s; red[wid + 32] = ss; }
    __syncthreads();
    if (wid == 0) {
        int nw = blockDim.x >> 5;
        s  = (lid < nw) ? red[lid] : 0.f;
        ss = (lid < nw) ? red[lid + 32] : 0.f;
        #pragma unroll
        for (int o = 16; o; o >>= 1) {
            s  += __shfl_xor_sync(0xffffffffu, s,  o);
            ss += __shfl_xor_sync(0xffffffffu, ss, o);
        }
        if (lid == 0) { red[0] = s; red[1] = ss; }
    }
    __syncthreads();
    const float inv_n = 1.f / (float)nelem;
    float mean = red[0] * inv_n;
    float var  = red[1] * inv_n - mean * mean;
    float rs   = rsqrtf(var + 1e-6f);
    int g = grp & (GROUPS - 1);
    for (int i = threadIdx.x; i < nelem; i += blockDim.x) {
        int c = g * CPG + (i >> 12);
        dst[i] = __float2bfloat16((src[i] - mean) * rs * scale[c] + bias[c]);
    }
}

// ---------------- bf16 transpose [C][A] -> [A][C], per batch z ----------------
__global__ void transpose_kernel(const bf16* __restrict__ src, bf16* __restrict__ dst) {
    __shared__ bf16 t[32][33];
    const bf16* s = src + (size_t)blockIdx.z * CK * AREA;
    bf16* d = dst + (size_t)blockIdx.z * AREA * CK;
    int a0 = blockIdx.x * 32, c0 = blockIdx.y * 32;
    for (int j = threadIdx.y; j < 32; j += 8)
        t[j][threadIdx.x] = s[(size_t)(c0 + j) * AREA + a0 + threadIdx.x];
    __syncthreads();
    for (int j = threadIdx.y; j < 32; j += 8)
        d[(size_t)(a0 + j) * CK + c0 + threadIdx.x] = t[threadIdx.x][j];
}

// ---------------- Row softmax over 4096 bf16 (in place, fp32 math) ----------------
__global__ void softmax_kernel(bf16* __restrict__ p) {
    bf16* r = p + (size_t)blockIdx.x * AREA;
    const int t = threadIdx.x;
    float v[16];
    float mx = -1e30f;
    #pragma unroll
    for (int j = 0; j < 16; j++) {
        v[j] = __bfloat162float(r[t + j * 256]);
        mx = fmaxf(mx, v[j]);
    }
    __shared__ float red[8];
    #pragma unroll
    for (int o = 16; o; o >>= 1) mx = fmaxf(mx, __shfl_xor_sync(0xffffffffu, mx, o));
    int wid = t >> 5, lid = t & 31;
    if (lid == 0) red[wid] = mx;
    __syncthreads();
    mx = red[lid & 7];
    #pragma unroll
    for (int o = 4; o; o >>= 1) mx = fmaxf(mx, __shfl_xor_sync(0xffffffffu, mx, o));
    float sum = 0.f;
    #pragma unroll
    for (int j = 0; j < 16; j++) { v[j] = __expf(v[j] - mx); sum += v[j]; }
    #pragma unroll
    for (int o = 16; o; o >>= 1) sum += __shfl_xor_sync(0xffffffffu, sum, o);
    if (lid == 0) red[wid] = sum;
    __syncthreads();
    sum = red[lid & 7];
    #pragma unroll
    for (int o = 4; o; o >>= 1) sum += __shfl_xor_sync(0xffffffffu, sum, o);
    float inv = 1.f / sum;
    #pragma unroll
    for (int j = 0; j < 16; j++) r[t + j * 256] = __float2bfloat16(v[j] * inv);
}

// ---------------- bf16 tensor-core GEMM ----------------
// C[b](M x N) = alpha * A[b] * B[b]^T  (+bias) (+res)
// A: [M][K] bf16 K-contig, B: [N][K] bf16 K-contig.
// CTA tile 128x256, warp tile 64x64 (8 warps, 2m x 4n), KCH=64, 3 stages.
// BIAS_MODE: 0 none, 1 per-m, 2 per-n.  OUT_BF16: bf16 vs fp32 out.

#define LDKE 72                           // padded smem row (64+8 bf16) -> conflict-free
#define KCH  64                           // K per stage
#define NST  3                            // pipeline stages
#define MATA_BYTES (128 * LDKE * 2)       // 18432 B  (A per stage)
#define MATB_BYTES (256 * LDKE * 2)       // 36864 B  (B per stage)
#define SMEM_GEMM (NST * (MATA_BYTES + MATB_BYTES))   // 165888 B

__device__ __forceinline__ void cpa16(uint32_t sm, const void* gm) {
    asm volatile("cp.async.ca.shared.global [%0], [%1], 16;" :: "r"(sm), "l"(gm));
}
__device__ __forceinline__ void ldm_x4(uint32_t& r0, uint32_t& r1, uint32_t& r2,
                                       uint32_t& r3, uint32_t addr) {
    asm volatile("ldmatrix.sync.aligned.m8n8.x4.shared.b16 {%0,%1,%2,%3}, [%4];"
                 : "=r"(r0), "=r"(r1), "=r"(r2), "=r"(r3) : "r"(addr));
}

template<int BIAS_MODE, int OUT_BF16, int HAS_RES>
__global__ void __launch_bounds__(256)
gemm_bf16(const bf16* __restrict__ A, size_t sA, int lda,
          const bf16* __restrict__ B, size_t sB, int ldb,
          void* __restrict__ Cv, size_t sC, int ldc,
          int K, float alpha, const float* __restrict__ bias,
          const float* __restrict__ res, size_t sR)
{
    extern __shared__ bf16 sm[];
    uint32_t smb;
    asm("{ .reg .u64 t; cvta.to.shared.u64 t, %1; cvt.u32.u64 %0, t; }"
        : "=r"(smb) : "l"(sm));
    const uint32_t BOFF = NST * MATA_BYTES;     // B stages start here

    const int bz = blockIdx.z;
    A += sA * bz; B += sB * bz;
    const int m0 = blockIdx.y * 128, n0 = blockIdx.x * 256;
    const int tid = threadIdx.x;
    const int wid = tid >> 5, lane = tid & 31;
    const int wm = (wid & 1) * 64, wn = (wid >> 1) * 64;
    const int sel = lane >> 3, l7 = lane & 7;

    // ldmatrix per-lane address parts (bf16-elem units)
    const uint32_t aLane = (uint32_t)(((sel & 1) * 8 + l7) * LDKE + ((sel & 2) ? 8 : 0));
    const uint32_t bLane = (uint32_t)((((sel & 2) ? 8 : 0) + l7) * LDKE + ((sel & 1) ? 8 : 0));

    float acc[4][8][4];
    #pragma unroll
    for (int i = 0; i < 4; i++)
        #pragma unroll
        for (int j = 0; j < 8; j++)
            #pragma unroll
            for (int r = 0; r < 4; r++) acc[i][j][r] = 0.f;

    const bf16* Abase = A + (size_t)m0 * lda;
    const bf16* Bbase = B + (size_t)n0 * ldb;
    const int nt = K / KCH;

    auto stage = [&](int s, int t) {
        uint32_t sa = smb + (uint32_t)s * MATA_BYTES;
        uint32_t sb = smb + BOFF + (uint32_t)s * MATB_BYTES;
        const bf16* Ags = Abase + (size_t)t * KCH;
        const bf16* Bgs = Bbase + (size_t)t * KCH;
        #pragma unroll
        for (int i = 0; i < 4; i++) {           // A: 128 rows x 8 segs
            int seg = i * 256 + tid;
            int row = seg >> 3, k16 = seg & 7;
            uint32_t off = (uint32_t)(row * (LDKE * 2) + k16 * 16);
            cpa16(sa + off, Ags + (size_t)row * lda + k16 * 8);
        }
        #pragma unroll
        for (int i = 0; i < 8; i++) {           // B: 256 rows x 8 segs
            int seg = i * 256 + tid;
            int row = seg >> 3, k16 = seg & 7;
            uint32_t off = (uint32_t)(row * (LDKE * 2) + k16 * 16);
            cpa16(sb + off, Bgs + (size_t)row * ldb + k16 * 8);
        }
        asm volatile("cp.async.commit_group;");
    };

    stage(0, 0);
    stage(1, 1);

    int s = 0;
    for (int t = 0; t < nt; t++) {
        if (t + 1 < nt) asm volatile("cp.async.wait_group 1;");
        else            asm volatile("cp.async.wait_group 0;");
        __syncthreads();

        if (t + 2 < nt) stage((t + 2) % NST, t + 2);

        const uint32_t sa = smb + (uint32_t)s * MATA_BYTES;
        const uint32_t sb = smb + BOFF + (uint32_t)s * MATB_BYTES;

        #pragma unroll
        for (int ks = 0; ks < 4; ks++) {
            uint32_t af[4][4], bfr[8][2];
            #pragma unroll
            for (int mt = 0; mt < 4; mt++) {
                uint32_t addr = sa + 2 * ((uint32_t)((wm + mt * 16) * LDKE) + aLane)
                              + (uint32_t)ks * 32;
                ldm_x4(af[mt][0], af[mt][1], af[mt][2], af[mt][3], addr);
            }
            #pragma unroll
            for (int p = 0; p < 4; p++) {
                uint32_t addr = sb + 2 * ((uint32_t)((wn + p * 16) * LDKE) + bLane)
                              + (uint32_t)ks * 32;
                ldm_x4(bfr[2 * p][0], bfr[2 * p][1], bfr[2 * p + 1][0], bfr[2 * p + 1][1], addr);
            }
            #pragma unroll
            for (int mt = 0; mt < 4; mt++)
                #pragma unroll
                for (int nn = 0; nn < 8; nn++)
                    asm volatile(
                        "mma.sync.aligned.m16n8k16.row.col.f32.bf16.bf16.f32 "
                        "{%0,%1,%2,%3}, {%4,%5,%6,%7}, {%8,%9}, {%0,%1,%2,%3};"
                        : "+f"(acc[mt][nn][0]), "+f"(acc[mt][nn][1]),
                          "+f"(acc[mt][nn][2]), "+f"(acc[mt][nn][3])
                        : "r"(af[mt][0]), "r"(af[mt][1]), "r"(af[mt][2]), "r"(af[mt][3]),
                          "r"(bfr[nn][0]), "r"(bfr[nn][1]));
        }
        s = (s + 1 == NST) ? 0 : s + 1;
    }

    // epilogue
    const int lq = lane >> 2, lr = lane & 3;
    float* Cf = (float*)Cv;
    bf16*  Cb = (bf16*)Cv;
    const size_t cbase = sC * bz;
    if (HAS_RES) res += sR * bz;

    #pragma unroll
    for (int mt = 0; mt < 4; mt++) {
        #pragma unroll
        for (int half = 0; half < 2; half++) {
            int m = m0 + wm + mt * 16 + lq + half * 8;
            float bm = (BIAS_MODE == 1) ? bias[m] : 0.f;
            #pragma unroll
            for (int nn = 0; nn < 8; nn++) {
                int n = n0 + wn + nn * 8 + 2 * lr;
                float c0 = acc[mt][nn][half * 2 + 0] * alpha;
                float c1 = acc[mt][nn][half * 2 + 1] * alpha;
                if (BIAS_MODE == 1) { c0 += bm; c1 += bm; }
                if (BIAS_MODE == 2) { c0 += bias[n]; c1 += bias[n + 1]; }
                if (OUT_BF16) {
                    __nv_bfloat162 p2;
                    p2.x = __float2bfloat16(c0);
                    p2.y = __float2bfloat16(c1);
                    *(__nv_bfloat162*)(Cb + cbase + (size_t)m * ldc + n) = p2;
                } else {
                    if (HAS_RES) {
                        c0 += res[(size_t)m * ldc + n];
                        c1 += res[(size_t)m * ldc + n + 1];
                    }
                    *(float2*)(Cf + cbase + (size_t)m * ldc + n) = make_float2(c0, c1);
                }
            }
        }
    }
}

// ---------------- launch ----------------
extern "C" void kernel_launch(void* const* d_in, const int* in_sizes, int n_in,
                              void* d_out, int out_size) {
    const float* net = (const float*)d_in[0];
    const float* gsc = (const float*)d_in[1];
    const float* gbi = (const float*)d_in[2];
    const float* wq  = (const float*)d_in[3];
    const float* bq  = (const float*)d_in[4];
    const float* wk  = (const float*)d_in[5];
    const float* bk  = (const float*)d_in[6];
    const float* wv  = (const float*)d_in[7];
    const float* bv  = (const float*)d_in[8];
    const float* wo  = (const float*)d_in[9];
    const float* bo  = (const float*)d_in[10];
    float* out = (float*)d_out;

    bf16 *xn, *xnT, *qT, *kT, *v, *OT, *S, *wb;
    cudaGetSymbolAddress((void**)&xn,  g_xn);
    cudaGetSymbolAddress((void**)&xnT, g_xnT);
    cudaGetSymbolAddress((void**)&qT,  g_qT);
    cudaGetSymbolAddress((void**)&kT,  g_kT);
    cudaGetSymbolAddress((void**)&v,   g_v);
    cudaGetSymbolAddress((void**)&OT,  g_OT);
    cudaGetSymbolAddress((void**)&S,   g_S);
    cudaGetSymbolAddress((void**)&wb,  g_wb);

    cudaFuncSetAttribute(gemm_bf16<2,1,0>, cudaFuncAttributeMaxDynamicSharedMemorySize, SMEM_GEMM);
    cudaFuncSetAttribute(gemm_bf16<1,1,0>, cudaFuncAttributeMaxDynamicSharedMemorySize, SMEM_GEMM);
    cudaFuncSetAttribute(gemm_bf16<0,1,0>, cudaFuncAttributeMaxDynamicSharedMemorySize, SMEM_GEMM);
    cudaFuncSetAttribute(gemm_bf16<1,0,1>, cudaFuncAttributeMaxDynamicSharedMemorySize, SMEM_GEMM);

    const size_t sAC = (size_t)AREA * CK;
    const size_t sCA = (size_t)CK * AREA;
    const size_t sSS = (size_t)AREA * AREA;
    const float attn_scale = 0.04419417382415922f;   // 512^-0.5

    cvt4_kernel<<<(4 * CK * CK) / 256, 256>>>(wq, wk, wv, wo, wb);
    groupnorm_kernel<<<BATCH * GROUPS, 512>>>(net, gsc, gbi, xn);
    transpose_kernel<<<dim3(AREA / 32, CK / 32, BATCH), dim3(32, 8)>>>(xn, xnT);

    dim3 blk(256);
    dim3 grdQK(CK / 256, AREA / 128, BATCH);     // (2, 32, 4)
    dim3 grdV (AREA / 256, CK / 128, BATCH);     // (16, 4, 4)
    dim3 grdS (AREA / 256, AREA / 128, BATCH);   // (16, 32, 4)

    // qT[a][c] = xnT[a][:] . wq[c][:] + bq[c]
    gemm_bf16<2,1,0><<<grdQK, blk, SMEM_GEMM>>>(
        xnT, sAC, CK,  wb + 0 * CK * CK, 0, CK,  qT, sAC, CK, CK, 1.f, bq, nullptr, 0);
    gemm_bf16<2,1,0><<<grdQK, blk, SMEM_GEMM>>>(
        xnT, sAC, CK,  wb + 1 * CK * CK, 0, CK,  kT, sAC, CK, CK, 1.f, bk, nullptr, 0);
    // v[c][a] = wv[c][:] . xnT[a][:] + bv[c]
    gemm_bf16<1,1,0><<<grdV, blk, SMEM_GEMM>>>(
        wb + 2 * CK * CK, 0, CK,  xnT, sAC, CK,  v, sCA, AREA, CK, 1.f, bv, nullptr, 0);
    // S[i][j] = scale * qT[i][:] . kT[j][:]
    gemm_bf16<0,1,0><<<grdS, blk, SMEM_GEMM>>>(
        qT, sAC, CK,  kT, sAC, CK,  S, sSS, AREA, CK, attn_scale, nullptr, nullptr, 0);

    softmax_kernel<<<BATCH * AREA, 256>>>(S);

    // OT[i][c] = P[i][:] . v[c][:]
    gemm_bf16<0,1,0><<<grdQK, blk, SMEM_GEMM>>>(
        S, sSS, AREA,  v, sCA, AREA,  OT, sAC, CK, AREA, 1.f, nullptr, nullptr, 0);
    // out[o][a] = wo[o][:] . OT[a][:] + bo[o] + net[o][a]
    gemm_bf16<1,0,1><<<grdV, blk, SMEM_GEMM>>>(
        wb + 3 * CK * CK, 0, CK,  OT, sAC, CK,  out, sCA, AREA, CK, 1.f, bo, net, sCA);
}